// round 1
// baseline (speedup 1.0000x reference)
#include <cuda_runtime.h>
#include <cuda_bf16.h>

// Problem constants
#define B_TOTAL   16384
#define N_IN      6
#define N_MF      5
#define N_FUZZ    30      // N_IN * N_MF
#define N_RULES   2048
#define N_OUT     2
#define BLOCK     128

// Packed rule: 6 byte-indices (values < 30) + precomputed output weights.
struct __align__(16) Rule {
    unsigned int b0;   // idx0..idx3, one byte each
    unsigned int b1;   // idx4, idx5 in low two bytes
    float ow0;         // out_centers[output_rules[r][0]]
    float ow1;         // out_centers[output_rules[r][1]]
};

__device__ Rule g_rules[N_RULES];   // scratch (no cudaMalloc allowed)

// ---------------------------------------------------------------------------
// Prep: pack rule indices + gather output centers. 2048 rules, trivial cost.
// ---------------------------------------------------------------------------
__global__ void pack_rules_kernel(const int* __restrict__ input_rules,
                                  const int* __restrict__ output_rules,
                                  const float* __restrict__ out_centers)
{
    int r = blockIdx.x * blockDim.x + threadIdx.x;
    if (r >= N_RULES) return;
    unsigned int b0 = 0, b1 = 0;
#pragma unroll
    for (int k = 0; k < 4; k++)
        b0 |= ((unsigned int)input_rules[r * N_IN + k] & 0xFFu) << (8 * k);
#pragma unroll
    for (int k = 0; k < 2; k++)
        b1 |= ((unsigned int)input_rules[r * N_IN + 4 + k] & 0xFFu) << (8 * k);
    Rule rr;
    rr.b0  = b0;
    rr.b1  = b1;
    rr.ow0 = out_centers[output_rules[r * N_OUT + 0]];
    rr.ow1 = out_centers[output_rules[r * N_OUT + 1]];
    g_rules[r] = rr;
}

// ---------------------------------------------------------------------------
// Main: one row per thread. Fuzz table in smem [idx][tid] (conflict-free),
// rules staged in smem (warp-uniform broadcast reads).
// ---------------------------------------------------------------------------
__global__ void __launch_bounds__(BLOCK) anfis_main_kernel(
    const float* __restrict__ x,
    const float* __restrict__ mf_centers,
    const float* __restrict__ mf_scales,
    float* __restrict__ out)
{
    __shared__ float s_fuzz[N_FUZZ * BLOCK];   // 15360 B
    __shared__ Rule  s_rules[N_RULES];         // 32768 B  (total 48128 <= 48KB)

    const int tid = threadIdx.x;
    const int row = blockIdx.x * BLOCK + tid;

    // ---- fuzzify: 30 values per row -> smem ----
    float xv[N_IN];
#pragma unroll
    for (int i = 0; i < N_IN; i++) xv[i] = x[row * N_IN + i];
#pragma unroll
    for (int i = 0; i < N_IN; i++) {
#pragma unroll
        for (int m = 0; m < N_MF; m++) {
            float c = mf_centers[i * N_MF + m];
            float s = mf_scales[i * N_MF + m];
            float z = (xv[i] - c) / s;
            s_fuzz[(i * N_MF + m) * BLOCK + tid] = __expf(-z * z);
        }
    }

    // ---- stage rules into smem (vectorized 16B) ----
    {
        const float4* gr = reinterpret_cast<const float4*>(g_rules);
        float4*       sr = reinterpret_cast<float4*>(s_rules);
        for (int i = tid; i < N_RULES; i += BLOCK) sr[i] = gr[i];
    }
    __syncthreads();

    // ---- rule loop ----
    float l1 = 0.0f, d0 = 0.0f, d1 = 0.0f;
    const float* fz = s_fuzz + tid;

#pragma unroll 4
    for (int r = 0; r < N_RULES; r++) {
        float4 rv = reinterpret_cast<const float4*>(s_rules)[r];  // LDS.128 broadcast
        unsigned int b0 = __float_as_uint(rv.x);
        unsigned int b1 = __float_as_uint(rv.y);

        float w = fz[__byte_perm(b0, 0, 0x4440) * BLOCK];
        w = fminf(w, fz[__byte_perm(b0, 0, 0x4441) * BLOCK]);
        w = fminf(w, fz[__byte_perm(b0, 0, 0x4442) * BLOCK]);
        w = fminf(w, fz[__byte_perm(b0, 0, 0x4443) * BLOCK]);
        w = fminf(w, fz[__byte_perm(b1, 0, 0x4440) * BLOCK]);
        w = fminf(w, fz[__byte_perm(b1, 0, 0x4441) * BLOCK]);

        l1 += w;                       // weights are exp(..) > 0: |w| == w
        d0 = fmaf(w, rv.z, d0);
        d1 = fmaf(w, rv.w, d1);
    }

    // ---- defuzz + tanh head ----
    float inv = 1.0f / fmaxf(l1, 1e-12f);
    out[row * 2 + 0] = tanhf(d0 * inv) * 4.0f;            // scale 4.0, center 0.0
    out[row * 2 + 1] = tanhf(d1 * inv) * 0.75f + 0.75f;   // scale 0.75, center 0.75
}

// ---------------------------------------------------------------------------
// Launch contract
// ---------------------------------------------------------------------------
extern "C" void kernel_launch(void* const* d_in, const int* in_sizes, int n_in,
                              void* d_out, int out_size)
{
    const float* x            = (const float*)d_in[0];
    const float* mf_centers   = (const float*)d_in[1];
    const float* mf_scales    = (const float*)d_in[2];
    const float* out_centers  = (const float*)d_in[3];
    const int*   input_rules  = (const int*)d_in[4];
    const int*   output_rules = (const int*)d_in[5];
    float*       out          = (float*)d_out;

    pack_rules_kernel<<<(N_RULES + 255) / 256, 256>>>(input_rules, output_rules, out_centers);
    anfis_main_kernel<<<B_TOTAL / BLOCK, BLOCK>>>(x, mf_centers, mf_scales, out);
}

// round 2
// speedup vs baseline: 1.5249x; 1.5249x over previous
#include <cuda_runtime.h>
#include <cuda_bf16.h>

// Problem constants
#define B_TOTAL   16384
#define N_IN      6
#define N_MF      5
#define N_FUZZ    30      // N_IN * N_MF
#define N_RULES   2048
#define N_OUT     2

// Main-kernel tiling
#define THREADS   1024
#define ROWS      128     // rows per block
#define PAIRS     64      // ROWS/2 (2 rows per thread via float2)
#define PARTS     16      // THREADS / PAIRS : rule partitions
#define RPP       (N_RULES / PARTS)   // 128 rules per thread

// Shared memory layout (dynamic, 71 KB total)
#define SMEM_FUZZ_BYTES   (N_FUZZ * ROWS * 4)            // 15360
#define SMEM_RULE_BYTES   (N_RULES * 16)                 // 32768
#define SMEM_RED_BYTES    (PAIRS * PARTS * 6 * 4)        // 24576
#define SMEM_TOTAL        (SMEM_FUZZ_BYTES + SMEM_RULE_BYTES + SMEM_RED_BYTES)

// Packed rule: 6 byte-indices (values < 30) + precomputed output weights.
struct __align__(16) Rule {
    unsigned int b0;   // idx0..idx3, one byte each
    unsigned int b1;   // idx4, idx5 in low two bytes
    float ow0;         // out_centers[output_rules[r][0]]
    float ow1;         // out_centers[output_rules[r][1]]
};

__device__ Rule g_rules[N_RULES];   // scratch (no cudaMalloc allowed)

// ---------------------------------------------------------------------------
// Prep: pack rule indices + gather output centers. 2048 rules, trivial cost.
// ---------------------------------------------------------------------------
__global__ void pack_rules_kernel(const int* __restrict__ input_rules,
                                  const int* __restrict__ output_rules,
                                  const float* __restrict__ out_centers)
{
    int r = blockIdx.x * blockDim.x + threadIdx.x;
    if (r >= N_RULES) return;
    unsigned int b0 = 0, b1 = 0;
#pragma unroll
    for (int k = 0; k < 4; k++)
        b0 |= ((unsigned int)input_rules[r * N_IN + k] & 0xFFu) << (8 * k);
#pragma unroll
    for (int k = 0; k < 2; k++)
        b1 |= ((unsigned int)input_rules[r * N_IN + 4 + k] & 0xFFu) << (8 * k);
    Rule rr;
    rr.b0  = b0;
    rr.b1  = b1;
    rr.ow0 = out_centers[output_rules[r * N_OUT + 0]];
    rr.ow1 = out_centers[output_rules[r * N_OUT + 1]];
    g_rules[r] = rr;
}

// ---------------------------------------------------------------------------
// Main: 128 rows per block, 2 rows per thread (float2 gathers), rules split
// across 16 partitions of 64 threads each -> 32 warps/SM for latency hiding.
// ---------------------------------------------------------------------------
__global__ void __launch_bounds__(THREADS) anfis_main_kernel(
    const float* __restrict__ x,
    const float* __restrict__ mf_centers,
    const float* __restrict__ mf_scales,
    float* __restrict__ out)
{
    extern __shared__ char smem[];
    float*  s_fuzz  = reinterpret_cast<float*>(smem);                       // [30][128]
    float4* s_rules = reinterpret_cast<float4*>(smem + SMEM_FUZZ_BYTES);    // [2048]
    float*  s_red   = reinterpret_cast<float*>(smem + SMEM_FUZZ_BYTES + SMEM_RULE_BYTES);

    const int tid  = threadIdx.x;
    const int pair = tid & (PAIRS - 1);   // which row-pair (0..63)
    const int part = tid >> 6;            // which rule partition (0..15)

    // ---- stage rules into smem (all threads, 16B vector copies) ----
    {
        const float4* gr = reinterpret_cast<const float4*>(g_rules);
        for (int i = tid; i < N_RULES; i += THREADS) s_rules[i] = gr[i];
    }

    // ---- fuzzify: first 128 threads, one row each ----
    if (tid < ROWS) {
        const int row = blockIdx.x * ROWS + tid;
        float xv[N_IN];
#pragma unroll
        for (int i = 0; i < N_IN; i++) xv[i] = x[row * N_IN + i];
#pragma unroll
        for (int i = 0; i < N_IN; i++) {
#pragma unroll
            for (int m = 0; m < N_MF; m++) {
                float c = mf_centers[i * N_MF + m];
                float s = mf_scales[i * N_MF + m];
                float z = (xv[i] - c) / s;
                s_fuzz[(i * N_MF + m) * ROWS + tid] = __expf(-z * z);
            }
        }
    }
    __syncthreads();

    // ---- rule loop: this thread covers 2 rows (pair) x 128 rules (part) ----
    // fuzz table viewed as float2[30][64]; lane-consecutive pairs -> conflict-free
    const float2* fz = reinterpret_cast<const float2*>(s_fuzz) + pair;

    float2 l1 = make_float2(0.f, 0.f);
    float2 d0 = make_float2(0.f, 0.f);
    float2 d1 = make_float2(0.f, 0.f);

    const int rbeg = part * RPP;
#pragma unroll 4
    for (int r = rbeg; r < rbeg + RPP; r++) {
        float4 rv = s_rules[r];                         // LDS.128 warp-uniform broadcast
        unsigned int b0 = __float_as_uint(rv.x);
        unsigned int b1 = __float_as_uint(rv.y);

        float2 w = fz[__byte_perm(b0, 0, 0x4440) * PAIRS];
        float2 t;
        t = fz[__byte_perm(b0, 0, 0x4441) * PAIRS]; w.x = fminf(w.x, t.x); w.y = fminf(w.y, t.y);
        t = fz[__byte_perm(b0, 0, 0x4442) * PAIRS]; w.x = fminf(w.x, t.x); w.y = fminf(w.y, t.y);
        t = fz[__byte_perm(b0, 0, 0x4443) * PAIRS]; w.x = fminf(w.x, t.x); w.y = fminf(w.y, t.y);
        t = fz[__byte_perm(b1, 0, 0x4440) * PAIRS]; w.x = fminf(w.x, t.x); w.y = fminf(w.y, t.y);
        t = fz[__byte_perm(b1, 0, 0x4441) * PAIRS]; w.x = fminf(w.x, t.x); w.y = fminf(w.y, t.y);

        l1.x += w.x;                      l1.y += w.y;          // weights > 0
        d0.x = fmaf(w.x, rv.z, d0.x);     d0.y = fmaf(w.y, rv.z, d0.y);
        d1.x = fmaf(w.x, rv.w, d1.x);     d1.y = fmaf(w.y, rv.w, d1.y);
    }

    // ---- cross-partition reduction through smem ----
    {
        float* dst = s_red + (pair * PARTS + part) * 6;
        dst[0] = l1.x; dst[1] = l1.y;
        dst[2] = d0.x; dst[3] = d0.y;
        dst[4] = d1.x; dst[5] = d1.y;
    }
    __syncthreads();

    if (tid < ROWS) {
        const int row  = tid;
        const int rp   = row >> 1;
        const int half = row & 1;
        float L = 0.f, D0 = 0.f, D1 = 0.f;
#pragma unroll
        for (int p = 0; p < PARTS; p++) {
            const float* src = s_red + (rp * PARTS + p) * 6;
            L  += src[0 + half];
            D0 += src[2 + half];
            D1 += src[4 + half];
        }
        float inv = 1.0f / fmaxf(L, 1e-12f);
        const int grow = blockIdx.x * ROWS + row;
        out[grow * 2 + 0] = tanhf(D0 * inv) * 4.0f;            // scale 4.0, center 0.0
        out[grow * 2 + 1] = tanhf(D1 * inv) * 0.75f + 0.75f;   // scale 0.75, center 0.75
    }
}

// ---------------------------------------------------------------------------
// Launch contract
// ---------------------------------------------------------------------------
extern "C" void kernel_launch(void* const* d_in, const int* in_sizes, int n_in,
                              void* d_out, int out_size)
{
    const float* x            = (const float*)d_in[0];
    const float* mf_centers   = (const float*)d_in[1];
    const float* mf_scales    = (const float*)d_in[2];
    const float* out_centers  = (const float*)d_in[3];
    const int*   input_rules  = (const int*)d_in[4];
    const int*   output_rules = (const int*)d_in[5];
    float*       out          = (float*)d_out;

    // Opt-in to >48KB dynamic smem (immediate API call; capture-safe, no alloc)
    static bool attr_set = false;
    if (!attr_set) {
        cudaFuncSetAttribute(anfis_main_kernel,
                             cudaFuncAttributeMaxDynamicSharedMemorySize, SMEM_TOTAL);
        attr_set = true;
    }

    pack_rules_kernel<<<(N_RULES + 255) / 256, 256>>>(input_rules, output_rules, out_centers);
    anfis_main_kernel<<<B_TOTAL / ROWS, THREADS, SMEM_TOTAL>>>(x, mf_centers, mf_scales, out);
}

// round 3
// speedup vs baseline: 1.9124x; 1.2541x over previous
#include <cuda_runtime.h>
#include <cuda_fp16.h>

// Problem constants
#define B_TOTAL   16384
#define N_IN      6
#define N_MF      5
#define N_FUZZ    30      // N_IN * N_MF
#define N_RULES   2048
#define N_OUT     2

// Main-kernel tiling
#define THREADS   1024
#define ROWS      128     // rows per block
#define PAIRS     64      // ROWS/2 (2 rows per thread via half2)
#define PARTS     16      // THREADS / PAIRS : rule partitions
#define RPP       (N_RULES / PARTS)   // 128 rules per thread

// Shared memory layout (dynamic)
#define SMEM_FUZZ_BYTES   (N_FUZZ * PAIRS * 4)           // 7680  (__half2 table)
#define SMEM_RULE_BYTES   (N_RULES * 16)                 // 32768
#define SMEM_RED_BYTES    (PAIRS * PARTS * 6 * 4)        // 24576
#define SMEM_TOTAL        (SMEM_FUZZ_BYTES + SMEM_RULE_BYTES + SMEM_RED_BYTES)  // 65024

// ---------------------------------------------------------------------------
// Single fused kernel:
//   phase 0: pack rules (byte indices + gathered out-centers) into smem
//   phase 1: fuzzify 128 rows into a half2 [30][64] table (2 rows per element)
//   phase 2: rule loop — 16 partitions x 64 pairs; LDS.32 gathers + hmin2
//   phase 3: cross-partition reduction + tanh head
// ---------------------------------------------------------------------------
__global__ void __launch_bounds__(THREADS) anfis_fused_kernel(
    const float* __restrict__ x,
    const float* __restrict__ mf_centers,
    const float* __restrict__ mf_scales,
    const float* __restrict__ out_centers,
    const int*   __restrict__ input_rules,
    const int*   __restrict__ output_rules,
    float* __restrict__ out)
{
    extern __shared__ char smem[];
    __half2* s_fuzz  = reinterpret_cast<__half2*>(smem);                      // [30][64]
    float4*  s_rules = reinterpret_cast<float4*>(smem + SMEM_FUZZ_BYTES);     // [2048]
    float*   s_red   = reinterpret_cast<float*>(smem + SMEM_FUZZ_BYTES + SMEM_RULE_BYTES);

    const int tid  = threadIdx.x;
    const int pair = tid & (PAIRS - 1);   // row-pair (0..63)
    const int part = tid >> 6;            // rule partition (0..15)

    // ---- phase 0: pack rules directly into smem (2 rules per thread) ----
#pragma unroll
    for (int rr = 0; rr < N_RULES / THREADS; rr++) {
        int r = tid + rr * THREADS;
        unsigned int b0 = 0, b1 = 0;
#pragma unroll
        for (int k = 0; k < 4; k++)
            b0 |= ((unsigned int)input_rules[r * N_IN + k] & 0xFFu) << (8 * k);
#pragma unroll
        for (int k = 0; k < 2; k++)
            b1 |= ((unsigned int)input_rules[r * N_IN + 4 + k] & 0xFFu) << (8 * k);
        float4 rv;
        rv.x = __uint_as_float(b0);
        rv.y = __uint_as_float(b1);
        rv.z = out_centers[output_rules[r * N_OUT + 0]];
        rv.w = out_centers[output_rules[r * N_OUT + 1]];
        s_rules[r] = rv;
    }

    // ---- phase 1: fuzzify (first 128 threads, one row each) ----
    if (tid < ROWS) {
        const int row = blockIdx.x * ROWS + tid;
        const int p   = tid >> 1;       // pair index
        const int h   = tid & 1;        // which half of the half2
        __half* fzh = reinterpret_cast<__half*>(s_fuzz);
        float xv[N_IN];
#pragma unroll
        for (int i = 0; i < N_IN; i++) xv[i] = x[row * N_IN + i];
#pragma unroll
        for (int i = 0; i < N_IN; i++) {
#pragma unroll
            for (int m = 0; m < N_MF; m++) {
                float c = mf_centers[i * N_MF + m];
                float s = mf_scales[i * N_MF + m];
                float z = (xv[i] - c) / s;
                fzh[((i * N_MF + m) * PAIRS + p) * 2 + h] = __float2half_rn(__expf(-z * z));
            }
        }
    }
    __syncthreads();

    // ---- phase 2: rule loop. LDS.32 gathers (conflict-free), hmin2 tree ----
    const __half2* fz = s_fuzz + pair;

    float l1x = 0.f, l1y = 0.f, d0x = 0.f, d0y = 0.f, d1x = 0.f, d1y = 0.f;

    const int rbeg = part * RPP;
#pragma unroll 4
    for (int r = rbeg; r < rbeg + RPP; r++) {
        float4 rv = s_rules[r];                         // LDS.128 warp-uniform broadcast
        unsigned int b0 = __float_as_uint(rv.x);
        unsigned int b1 = __float_as_uint(rv.y);

        __half2 g0 = fz[__byte_perm(b0, 0, 0x4440) * PAIRS];
        __half2 g1 = fz[__byte_perm(b0, 0, 0x4441) * PAIRS];
        __half2 g2 = fz[__byte_perm(b0, 0, 0x4442) * PAIRS];
        __half2 g3 = fz[__byte_perm(b0, 0, 0x4443) * PAIRS];
        __half2 g4 = fz[__byte_perm(b1, 0, 0x4440) * PAIRS];
        __half2 g5 = fz[__byte_perm(b1, 0, 0x4441) * PAIRS];

        __half2 w = __hmin2(__hmin2(__hmin2(g0, g1), __hmin2(g2, g3)), __hmin2(g4, g5));
        float2 wf = __half22float2(w);

        l1x += wf.x;                    l1y += wf.y;          // weights > 0
        d0x = fmaf(wf.x, rv.z, d0x);    d0y = fmaf(wf.y, rv.z, d0y);
        d1x = fmaf(wf.x, rv.w, d1x);    d1y = fmaf(wf.y, rv.w, d1y);
    }

    // ---- phase 3: cross-partition reduction through smem ----
    {
        float* dst = s_red + (pair * PARTS + part) * 6;
        dst[0] = l1x; dst[1] = l1y;
        dst[2] = d0x; dst[3] = d0y;
        dst[4] = d1x; dst[5] = d1y;
    }
    __syncthreads();

    if (tid < ROWS) {
        const int row  = tid;
        const int rp   = row >> 1;
        const int half = row & 1;
        float L = 0.f, D0 = 0.f, D1 = 0.f;
#pragma unroll
        for (int p = 0; p < PARTS; p++) {
            const float* src = s_red + (rp * PARTS + p) * 6;
            L  += src[0 + half];
            D0 += src[2 + half];
            D1 += src[4 + half];
        }
        float inv = 1.0f / fmaxf(L, 1e-12f);
        const int grow = blockIdx.x * ROWS + row;
        out[grow * 2 + 0] = tanhf(D0 * inv) * 4.0f;            // scale 4.0, center 0.0
        out[grow * 2 + 1] = tanhf(D1 * inv) * 0.75f + 0.75f;   // scale 0.75, center 0.75
    }
}

// ---------------------------------------------------------------------------
// Launch contract
// ---------------------------------------------------------------------------
extern "C" void kernel_launch(void* const* d_in, const int* in_sizes, int n_in,
                              void* d_out, int out_size)
{
    const float* x            = (const float*)d_in[0];
    const float* mf_centers   = (const float*)d_in[1];
    const float* mf_scales    = (const float*)d_in[2];
    const float* out_centers  = (const float*)d_in[3];
    const int*   input_rules  = (const int*)d_in[4];
    const int*   output_rules = (const int*)d_in[5];
    float*       out          = (float*)d_out;

    // Opt-in to >48KB dynamic smem (immediate API call; capture-safe, no alloc)
    static bool attr_set = false;
    if (!attr_set) {
        cudaFuncSetAttribute(anfis_fused_kernel,
                             cudaFuncAttributeMaxDynamicSharedMemorySize, SMEM_TOTAL);
        attr_set = true;
    }

    anfis_fused_kernel<<<B_TOTAL / ROWS, THREADS, SMEM_TOTAL>>>(
        x, mf_centers, mf_scales, out_centers, input_rules, output_rules, out);
}

// round 4
// speedup vs baseline: 2.2998x; 1.2025x over previous
#include <cuda_runtime.h>
#include <cuda_fp16.h>

// Problem constants
#define B_TOTAL   16384
#define N_IN      6
#define N_MF      5
#define N_FUZZ    30      // N_IN * N_MF
#define N_RULES   2048
#define N_OUT     2

// Main-kernel tiling: 128 rows/block, 4 rows per thread (uint2 = 2x half2)
#define THREADS   1024
#define ROWS      128
#define QUADS     32      // ROWS/4
#define PARTS     32      // THREADS / QUADS : rule partitions
#define RPP       (N_RULES / PARTS)   // 64 rules per thread

// Shared memory layout (dynamic). Reduction buffer OVERLAPS the rule buffer
// (rules are dead after the rule loop; sync-separated).
#define SMEM_FUZZ_BYTES   (N_FUZZ * QUADS * 8)           // 7680  (uint2 table)
#define SMEM_RULE_BYTES   (N_RULES * 16)                 // 32768
#define SMEM_RED_BYTES    (QUADS * PARTS * 12 * 4)       // 49152
#define SMEM_TOTAL        (SMEM_FUZZ_BYTES + SMEM_RED_BYTES)   // 56832

// ---------------------------------------------------------------------------
// Fused kernel:
//   phase 0: pack rules (byte idx + out-center floats) into smem
//   phase 1: fuzzify 128 rows into half2x2 [30][32] table (4 rows per uint2)
//   phase 2: rule loop — 32 partitions x 32 quads; LDS.64 gathers + hmin2
//   phase 3: cross-partition reduction + tanh head
// ---------------------------------------------------------------------------
__global__ void __launch_bounds__(THREADS) anfis_fused_kernel(
    const float* __restrict__ x,
    const float* __restrict__ mf_centers,
    const float* __restrict__ mf_scales,
    const float* __restrict__ out_centers,
    const int*   __restrict__ input_rules,
    const int*   __restrict__ output_rules,
    float* __restrict__ out)
{
    extern __shared__ char smem[];
    uint2*  s_fuzz  = reinterpret_cast<uint2*>(smem);                       // [30][32]
    float4* s_rules = reinterpret_cast<float4*>(smem + SMEM_FUZZ_BYTES);    // [2048] (dies after loop)
    float*  s_red   = reinterpret_cast<float*>(smem + SMEM_FUZZ_BYTES);     // overlaps rules

    const int tid  = threadIdx.x;
    const int quad = tid & (QUADS - 1);   // row-quad (0..31)
    const int part = tid >> 5;            // rule partition (0..31)

    // ---- phase 0: pack rules directly into smem (2 rules per thread) ----
#pragma unroll
    for (int rr = 0; rr < N_RULES / THREADS; rr++) {
        int r = tid + rr * THREADS;
        unsigned int b0 = 0, b1 = 0;
#pragma unroll
        for (int k = 0; k < 4; k++)
            b0 |= ((unsigned int)input_rules[r * N_IN + k] & 0xFFu) << (8 * k);
#pragma unroll
        for (int k = 0; k < 2; k++)
            b1 |= ((unsigned int)input_rules[r * N_IN + 4 + k] & 0xFFu) << (8 * k);
        float4 rv;
        rv.x = __uint_as_float(b0);
        rv.y = __uint_as_float(b1);
        rv.z = out_centers[output_rules[r * N_OUT + 0]];
        rv.w = out_centers[output_rules[r * N_OUT + 1]];
        s_rules[r] = rv;
    }

    // ---- phase 1: fuzzify (first 128 threads, one row each) ----
    if (tid < ROWS) {
        const int row = blockIdx.x * ROWS + tid;
        const int q   = tid >> 2;       // quad index
        const int h   = tid & 3;        // slot within quad
        __half* fzh = reinterpret_cast<__half*>(s_fuzz);
        float xv[N_IN];
#pragma unroll
        for (int i = 0; i < N_IN; i++) xv[i] = x[row * N_IN + i];
#pragma unroll
        for (int i = 0; i < N_IN; i++) {
#pragma unroll
            for (int m = 0; m < N_MF; m++) {
                float c = mf_centers[i * N_MF + m];
                float s = mf_scales[i * N_MF + m];
                float z = (xv[i] - c) / s;
                fzh[((i * N_MF + m) * QUADS + q) * 4 + h] = __float2half_rn(__expf(-z * z));
            }
        }
    }
    __syncthreads();

    // ---- phase 2: rule loop. LDS.64 gathers (conflict-free), 2x hmin2 trees ----
    const uint2* fz = s_fuzz + quad;

    float l1a = 0.f, l1b = 0.f, l1c = 0.f, l1d = 0.f;
    float d0a = 0.f, d0b = 0.f, d0c = 0.f, d0d = 0.f;
    float d1a = 0.f, d1b = 0.f, d1c = 0.f, d1d = 0.f;

    const int rbeg = part * RPP;
#pragma unroll 4
    for (int r = rbeg; r < rbeg + RPP; r++) {
        float4 rv = s_rules[r];                         // LDS.128 warp-uniform broadcast
        unsigned int b0 = __float_as_uint(rv.x);
        unsigned int b1 = __float_as_uint(rv.y);

        uint2 g0 = fz[__byte_perm(b0, 0, 0x4440) * QUADS];
        uint2 g1 = fz[__byte_perm(b0, 0, 0x4441) * QUADS];
        uint2 g2 = fz[__byte_perm(b0, 0, 0x4442) * QUADS];
        uint2 g3 = fz[__byte_perm(b0, 0, 0x4443) * QUADS];
        uint2 g4 = fz[__byte_perm(b1, 0, 0x4440) * QUADS];
        uint2 g5 = fz[__byte_perm(b1, 0, 0x4441) * QUADS];

        // min-tree on the two packed lanes (rows 0,1 in .x; rows 2,3 in .y)
        __half2 mx = __hmin2(__hmin2(__hmin2(*(__half2*)&g0.x, *(__half2*)&g1.x),
                                     __hmin2(*(__half2*)&g2.x, *(__half2*)&g3.x)),
                             __hmin2(*(__half2*)&g4.x, *(__half2*)&g5.x));
        __half2 my = __hmin2(__hmin2(__hmin2(*(__half2*)&g0.y, *(__half2*)&g1.y),
                                     __hmin2(*(__half2*)&g2.y, *(__half2*)&g3.y)),
                             __hmin2(*(__half2*)&g4.y, *(__half2*)&g5.y));

        float2 wx = __half22float2(mx);
        float2 wy = __half22float2(my);

        l1a += wx.x;  l1b += wx.y;  l1c += wy.x;  l1d += wy.y;   // weights > 0
        d0a = fmaf(wx.x, rv.z, d0a);  d0b = fmaf(wx.y, rv.z, d0b);
        d0c = fmaf(wy.x, rv.z, d0c);  d0d = fmaf(wy.y, rv.z, d0d);
        d1a = fmaf(wx.x, rv.w, d1a);  d1b = fmaf(wx.y, rv.w, d1b);
        d1c = fmaf(wy.x, rv.w, d1c);  d1d = fmaf(wy.y, rv.w, d1d);
    }

    // Rules region is dead; reduction buffer overlaps it.
    __syncthreads();

    // ---- phase 3: cross-partition reduction through smem ----
    {
        float* dst = s_red + (quad * PARTS + part) * 12;
        dst[0] = l1a; dst[1]  = l1b; dst[2]  = l1c; dst[3]  = l1d;
        dst[4] = d0a; dst[5]  = d0b; dst[6]  = d0c; dst[7]  = d0d;
        dst[8] = d1a; dst[9]  = d1b; dst[10] = d1c; dst[11] = d1d;
    }
    __syncthreads();

    if (tid < ROWS) {
        const int row = tid;
        const int q   = row >> 2;
        const int sub = row & 3;
        float L = 0.f, D0 = 0.f, D1 = 0.f;
#pragma unroll
        for (int p = 0; p < PARTS; p++) {
            const float* src = s_red + (q * PARTS + p) * 12;
            L  += src[0 + sub];
            D0 += src[4 + sub];
            D1 += src[8 + sub];
        }
        float inv = 1.0f / fmaxf(L, 1e-12f);
        const int grow = blockIdx.x * ROWS + row;
        out[grow * 2 + 0] = tanhf(D0 * inv) * 4.0f;            // scale 4.0, center 0.0
        out[grow * 2 + 1] = tanhf(D1 * inv) * 0.75f + 0.75f;   // scale 0.75, center 0.75
    }
}

// ---------------------------------------------------------------------------
// Launch contract
// ---------------------------------------------------------------------------
extern "C" void kernel_launch(void* const* d_in, const int* in_sizes, int n_in,
                              void* d_out, int out_size)
{
    const float* x            = (const float*)d_in[0];
    const float* mf_centers   = (const float*)d_in[1];
    const float* mf_scales    = (const float*)d_in[2];
    const float* out_centers  = (const float*)d_in[3];
    const int*   input_rules  = (const int*)d_in[4];
    const int*   output_rules = (const int*)d_in[5];
    float*       out          = (float*)d_out;

    // Opt-in to >48KB dynamic smem (immediate API call; capture-safe, no alloc)
    static bool attr_set = false;
    if (!attr_set) {
        cudaFuncSetAttribute(anfis_fused_kernel,
                             cudaFuncAttributeMaxDynamicSharedMemorySize, SMEM_TOTAL);
        attr_set = true;
    }

    anfis_fused_kernel<<<B_TOTAL / ROWS, THREADS, SMEM_TOTAL>>>(
        x, mf_centers, mf_scales, out_centers, input_rules, output_rules, out);
}